// round 11
// baseline (speedup 1.0000x reference)
#include <cuda_runtime.h>
#include <math.h>

#define NN 50000
#define EE 800000
#define DD 128

// ---------------- scratch (static __device__, no allocs) ----------------
__device__ float g_z[NN * DD];      // h @ W_func^T
__device__ float g_hs[NN * DD];     // h @ W_self^T
__device__ float g_ssrc[NN];
__device__ float g_sdst[NN];
__device__ float g_se[EE];          // per-edge attention dot
__device__ int   g_deg[NN];
__device__ int   g_cursor[NN];
__device__ int   g_off[NN + 1];
__device__ unsigned long long g_pair[EE];   // (logit<<32 | src) sorted by dst

// ---------------- helpers ----------------
__device__ __forceinline__ unsigned f2tf(float x) {
    unsigned r;
    asm("cvt.rna.tf32.f32 %0, %1;" : "=r"(r) : "f"(x));
    return r;
}

__device__ __forceinline__ void mma_tf32(float* c, unsigned a0, unsigned a1,
                                         unsigned a2, unsigned a3,
                                         unsigned b0, unsigned b1) {
    asm volatile(
        "mma.sync.aligned.m16n8k8.row.col.f32.tf32.tf32.f32 "
        "{%0,%1,%2,%3},{%4,%5,%6,%7},{%8,%9},{%0,%1,%2,%3};\n"
        : "+f"(c[0]), "+f"(c[1]), "+f"(c[2]), "+f"(c[3])
        : "r"(a0), "r"(a1), "r"(a2), "r"(a3), "r"(b0), "r"(b1));
}

__device__ __forceinline__ float warp_sum(float v) {
    #pragma unroll
    for (int o = 16; o; o >>= 1) v += __shfl_xor_sync(0xFFFFFFFFu, v, o);
    return v;
}

// ---------------- degree histogram (dst only) ----------------
__global__ void k_deg(const int* __restrict__ dst, int E) {
    int e = blockIdx.x * blockDim.x + threadIdx.x;
    if (e < E) atomicAdd(&g_deg[dst[e]], 1);
}

// ---------------- dual tf32 GEMM (h_s and z) + fused rowdots ----------------
__global__ __launch_bounds__(256, 1) void k_gemm_dual(
    const float* __restrict__ h, const float* __restrict__ Ws,
    const float* __restrict__ Wf, const float* __restrict__ Watt, int N) {
    extern __shared__ float smem[];
    float* sH = smem;                                  // 128*132 f32
    unsigned* sW = (unsigned*)(smem + 128 * 132);      // 128*132 tf32 bits

    int tid = threadIdx.x;
    int lane = tid & 31, w = tid >> 5;
    int tg = lane & 3, gid = lane >> 2;
    int row0 = blockIdx.x * 128;

    for (int i = tid; i < 128 * 32; i += 256) {
        int r = i >> 5, c4 = i & 31;
        float4 v = make_float4(0.f, 0.f, 0.f, 0.f);
        if (row0 + r < N) v = ((const float4*)h)[(size_t)(row0 + r) * 32 + c4];
        *(float4*)&sH[r * 132 + c4 * 4] = v;
    }
    __syncthreads();

    unsigned a[2][32];
    int ar0 = w * 16 + gid;
    #pragma unroll
    for (int j = 0; j < 32; j++) {
        a[0][j] = f2tf(sH[ar0 * 132 + tg + 4 * j]);
        a[1][j] = f2tf(sH[(ar0 + 8) * 132 + tg + 4 * j]);
    }

    const float* Wm[2] = {Ws, Wf};
    float* Om[2] = {g_hs, g_z};

    for (int m = 0; m < 2; m++) {
        __syncthreads();
        const float* W = Wm[m];
        for (int i = tid; i < 128 * 128; i += 256) {
            int r = i >> 7, c = i & 127;
            sW[r * 132 + c] = f2tf(W[i]);
        }
        __syncthreads();

        float acc[16][4];
        #pragma unroll
        for (int nt = 0; nt < 16; nt++)
            #pragma unroll
            for (int q = 0; q < 4; q++) acc[nt][q] = 0.f;

        #pragma unroll
        for (int kt = 0; kt < 16; kt++) {
            unsigned a0 = a[0][2 * kt], a2 = a[0][2 * kt + 1];
            unsigned a1 = a[1][2 * kt], a3 = a[1][2 * kt + 1];
            #pragma unroll
            for (int nt = 0; nt < 16; nt++) {
                unsigned b0 = sW[(nt * 8 + gid) * 132 + kt * 8 + tg];
                unsigned b1 = sW[(nt * 8 + gid) * 132 + kt * 8 + tg + 4];
                mma_tf32(acc[nt], a0, a1, a2, a3, b0, b1);
            }
        }

        float* O = Om[m];
        int r1 = row0 + ar0;
        int r2 = r1 + 8;
        #pragma unroll
        for (int nt = 0; nt < 16; nt++) {
            int col = nt * 8 + tg * 2;
            if (r1 < N) *(float2*)&O[(size_t)r1 * 128 + col] = make_float2(acc[nt][0], acc[nt][1]);
            if (r2 < N) *(float2*)&O[(size_t)r2 * 128 + col] = make_float2(acc[nt][2], acc[nt][3]);
        }

        if (m == 1) {
            float p1a = 0.f, p1b = 0.f, p2a = 0.f, p2b = 0.f;
            #pragma unroll
            for (int nt = 0; nt < 16; nt++) {
                int c0 = nt * 8 + tg * 2;
                float wa0 = Watt[c0],        wa1 = Watt[c0 + 1];
                float wb0 = Watt[128 + c0],  wb1 = Watt[128 + c0 + 1];
                p1a += acc[nt][0] * wa0 + acc[nt][1] * wa1;
                p1b += acc[nt][0] * wb0 + acc[nt][1] * wb1;
                p2a += acc[nt][2] * wa0 + acc[nt][3] * wa1;
                p2b += acc[nt][2] * wb0 + acc[nt][3] * wb1;
            }
            #pragma unroll
            for (int o = 1; o < 4; o <<= 1) {
                p1a += __shfl_xor_sync(0xFFFFFFFFu, p1a, o);
                p1b += __shfl_xor_sync(0xFFFFFFFFu, p1b, o);
                p2a += __shfl_xor_sync(0xFFFFFFFFu, p2a, o);
                p2b += __shfl_xor_sync(0xFFFFFFFFu, p2b, o);
            }
            if (tg == 0) {
                if (r1 < N) { g_ssrc[r1] = p1a; g_sdst[r1] = p1b; }
                if (r2 < N) { g_ssrc[r2] = p2a; g_sdst[r2] = p2b; }
            }
        }
    }
}

// ---------------- edge pre-dot: s_e = edge_w . wa[256:384]  (16 edges/warp) ----------------
__global__ __launch_bounds__(256) void k_edge_se(const float* __restrict__ ew,
                                                 const float* __restrict__ Watt, int E) {
    int wid = (blockIdx.x * blockDim.x + threadIdx.x) >> 5;
    int lane = threadIdx.x & 31;
    int base = wid * 16;
    if (base >= E) return;

    float4 w4 = ((const float4*)Watt)[64 + lane];   // wa[256:384]

    float s[16];
    #pragma unroll
    for (int j = 0; j < 16; j++) {
        float4 e4 = make_float4(0.f, 0.f, 0.f, 0.f);
        if (base + j < E) e4 = ((const float4*)ew)[(size_t)(base + j) * 32 + lane];
        s[j] = e4.x * w4.x + e4.y * w4.y + e4.z * w4.z + e4.w * w4.w;
    }

    #pragma unroll
    for (int o = 16; o; o >>= 1) {
        #pragma unroll
        for (int j = 0; j < 16; j++)
            s[j] += __shfl_xor_sync(0xFFFFFFFFu, s[j], o);
    }

    if (lane < 16) {
        int e = base + lane;
        if (e < E) {
            float se = s[0];
            #pragma unroll
            for (int j = 1; j < 16; j++)
                if (lane == j) se = s[j];
            g_se[e] = se;
        }
    }
}

// ---------------- single-block fused scan (g_deg -> g_off/g_cursor) ----------------
__global__ __launch_bounds__(1024) void k_scan(int N) {
    __shared__ int wsum[32];
    int tid = threadIdx.x, lane = tid & 31, w = tid >> 5;
    int base = 0;
    int nchunk = (N + 1023) >> 10;
    for (int c = 0; c < nchunk; c++) {
        int i = (c << 10) + tid;
        int v = (i < N) ? g_deg[i] : 0;
        int x = v;
        #pragma unroll
        for (int o = 1; o < 32; o <<= 1) {
            int t = __shfl_up_sync(0xFFFFFFFFu, x, o);
            if (lane >= o) x += t;
        }
        if (lane == 31) wsum[w] = x;
        __syncthreads();
        if (w == 0) {
            int y = wsum[lane];
            #pragma unroll
            for (int o = 1; o < 32; o <<= 1) {
                int t = __shfl_up_sync(0xFFFFFFFFu, y, o);
                if (lane >= o) y += t;
            }
            wsum[lane] = y;
        }
        __syncthreads();
        int woff = (w == 0) ? 0 : wsum[w - 1];
        int excl = base + woff + x - v;
        if (i < N) { g_off[i] = excl; g_cursor[i] = excl; }
        int tot = wsum[31];
        __syncthreads();
        base += tot;
    }
    if (tid == 0) g_off[N] = base;
}

// ---------------- edge final: logit + dst-sorted scatter ----------------
__global__ void k_edge_final(const int* __restrict__ src,
                             const int* __restrict__ dst, int E) {
    int e = blockIdx.x * blockDim.x + threadIdx.x;
    if (e >= E) return;
    int d = dst[e];
    int sc = src[e];
    float l = g_ssrc[sc] + g_sdst[d] + g_se[e];
    l = l > 0.f ? l : 0.01f * l;
    int p = atomicAdd(&g_cursor[d], 1);
    g_pair[p] = ((unsigned long long)__float_as_uint(l) << 32) | (unsigned)sc;
}

// ---------------- per-dst softmax + weighted gather + epilogue ----------------
__global__ __launch_bounds__(256, 3) void k_aggregate(const float* __restrict__ h,
                                                      float* __restrict__ out, int N) {
    __shared__ float swl[8][32];
    __shared__ int   ssv[8][32];
    int w = threadIdx.x >> 5;
    int lane = threadIdx.x & 31;
    int wid = (blockIdx.x * blockDim.x + threadIdx.x) >> 5;
    if (wid >= N) return;

    int beg = g_off[wid], end = g_off[wid + 1];
    int deg = end - beg;
    float4 hv = ((const float4*)h)[(size_t)wid * 32 + lane];
    float4 res;

    if (deg == 0) {
        res.x = hv.x + fmaxf(hv.x, 0.f);
        res.y = hv.y + fmaxf(hv.y, 0.f);
        res.z = hv.z + fmaxf(hv.z, 0.f);
        res.w = hv.w + fmaxf(hv.w, 0.f);
    } else {
        float4 acc = make_float4(0.f, 0.f, 0.f, 0.f);
        float denom = 0.f;

        if (deg <= 32) {
            // fast path: single chunk, weights staged in smem
            unsigned long long u = 0;
            float lg = -INFINITY;
            if (lane < deg) {
                u = g_pair[beg + lane];
                lg = __uint_as_float((unsigned)(u >> 32));
            }
            float m = lg;
            #pragma unroll
            for (int o = 16; o; o >>= 1)
                m = fmaxf(m, __shfl_xor_sync(0xFFFFFFFFu, m, o));
            float wl = (lane < deg) ? __expf(lg - m) : 0.f;
            denom = wl;
            swl[w][lane] = wl;
            ssv[w][lane] = (int)(unsigned)u;
            __syncwarp();

            int k = 0;
            for (; k + 8 <= deg; k += 8) {
                float4 zb[8];
                #pragma unroll
                for (int j = 0; j < 8; j++) {
                    int aj = ssv[w][k + j];
                    zb[j] = ((const float4*)g_z)[(size_t)aj * 32 + lane];
                }
                #pragma unroll
                for (int j = 0; j < 8; j++) {
                    float wk = swl[w][k + j];
                    acc.x += wk * zb[j].x;
                    acc.y += wk * zb[j].y;
                    acc.z += wk * zb[j].z;
                    acc.w += wk * zb[j].w;
                }
            }
            for (; k < deg; k++) {
                float wk = swl[w][k];
                int   ak = ssv[w][k];
                float4 z0 = ((const float4*)g_z)[(size_t)ak * 32 + lane];
                acc.x += wk * z0.x;
                acc.y += wk * z0.y;
                acc.z += wk * z0.z;
                acc.w += wk * z0.w;
            }
        } else {
            // rare path (P ~ 1e-4): simple two-pass serial loop
            float m = -INFINITY;
            for (int i = beg + lane; i < end; i += 32)
                m = fmaxf(m, __uint_as_float((unsigned)(g_pair[i] >> 32)));
            #pragma unroll
            for (int o = 16; o; o >>= 1)
                m = fmaxf(m, __shfl_xor_sync(0xFFFFFFFFu, m, o));

            for (int i = beg; i < end; i++) {
                unsigned long long u = g_pair[i];     // same addr: broadcast
                float wl = __expf(__uint_as_float((unsigned)(u >> 32)) - m);
                int   sv = (int)(unsigned)u;
                if (lane == 0) denom += wl;
                float4 z0 = ((const float4*)g_z)[(size_t)sv * 32 + lane];
                acc.x += wl * z0.x;
                acc.y += wl * z0.y;
                acc.z += wl * z0.z;
                acc.w += wl * z0.w;
            }
        }

        denom = warp_sum(denom);
        float inv = 1.f / fmaxf(denom, 1e-9f);
        float4 hs = ((const float4*)g_hs)[(size_t)wid * 32 + lane];
        float tx = hs.x + acc.x * inv;
        float ty = hs.y + acc.y * inv;
        float tz = hs.z + acc.z * inv;
        float tw = hs.w + acc.w * inv;
        res.x = hv.x + fmaxf(tx, 0.f);
        res.y = hv.y + fmaxf(ty, 0.f);
        res.z = hv.z + fmaxf(tz, 0.f);
        res.w = hv.w + fmaxf(tw, 0.f);
    }
    ((float4*)out)[(size_t)wid * 32 + lane] = res;
}

// ---------------- launch (fork/join across 3 streams) ----------------
extern "C" void kernel_launch(void* const* d_in, const int* in_sizes, int n_in,
                              void* d_out, int out_size) {
    const float* h    = (const float*)d_in[0];
    const float* ew   = (const float*)d_in[1];
    const float* Ws   = (const float*)d_in[2];
    const float* Wf   = (const float*)d_in[3];
    const float* Watt = (const float*)d_in[4];
    const int*   src  = (const int*)d_in[5];
    const int*   dst  = (const int*)d_in[6];
    float* out = (float*)d_out;

    int N = in_sizes[0] / DD;
    int E = in_sizes[5];

    static cudaStream_t sA = nullptr, sB = nullptr;
    static cudaEvent_t evFork = nullptr, evA = nullptr, evB = nullptr;
    if (sA == nullptr) {
        cudaStreamCreateWithFlags(&sA, cudaStreamNonBlocking);
        cudaStreamCreateWithFlags(&sB, cudaStreamNonBlocking);
        cudaEventCreateWithFlags(&evFork, cudaEventDisableTiming);
        cudaEventCreateWithFlags(&evA, cudaEventDisableTiming);
        cudaEventCreateWithFlags(&evB, cudaEventDisableTiming);
        size_t gemm_smem = (size_t)(128 * 132) * 4 * 2;
        cudaFuncSetAttribute(k_gemm_dual,
                             cudaFuncAttributeMaxDynamicSharedMemorySize,
                             (int)gemm_smem);
    }
    size_t gemm_smem = (size_t)(128 * 132) * 4 * 2;

    // fork
    cudaEventRecord(evFork, 0);
    cudaStreamWaitEvent(sA, evFork, 0);
    cudaStreamWaitEvent(sB, evFork, 0);

    // stream A: the 410MB edge_w stream (DRAM-bound, no deps)
    int ewarps = (E + 15) / 16;
    k_edge_se<<<(ewarps + 7) / 8, 256, 0, sA>>>(ew, Watt, E);
    cudaEventRecord(evA, sA);

    // stream B: the GEMM (tensor/issue-bound)
    k_gemm_dual<<<(N + 127) / 128, 256, gemm_smem, sB>>>(h, Ws, Wf, Watt, N);
    cudaEventRecord(evB, sB);

    // main stream: deg histogram + fused scan (tiny, hides under A/B)
    void* degp = nullptr;
    cudaGetSymbolAddress(&degp, g_deg);
    cudaMemsetAsync(degp, 0, (size_t)N * sizeof(int), 0);
    k_deg<<<(E + 255) / 256, 256>>>(dst, E);
    k_scan<<<1, 1024>>>(N);

    // join
    cudaStreamWaitEvent(0, evA, 0);
    cudaStreamWaitEvent(0, evB, 0);

    // final logit + dst-sorted scatter, then aggregation
    k_edge_final<<<(E + 255) / 256, 256>>>(src, dst, E);
    k_aggregate<<<(N + 7) / 8, 256>>>(h, out, N);
}